// round 1
// baseline (speedup 1.0000x reference)
#include <cuda_runtime.h>
#include <math.h>

#define IN_DIM 256
#define OUT_DIM 256
#define BATCH 2
#define MAXN 10240
#define MAXE 163840
#define SLOPE 0.2f

// ---------------- scratch (static device globals; no allocation) ----------
static __device__ float g_src_proj[MAXN * BATCH * OUT_DIM];   // 20 MB
static __device__ float g_vals[MAXN * BATCH * OUT_DIM];       // 20 MB
static __device__ float g_sdot[MAXN * BATCH];
static __device__ float g_tdot[MAXN * BATCH];
static __device__ float g_denom[MAXN * BATCH];
static __device__ float g_ex[MAXE * BATCH];                   // ex, then alpha in-place
static __device__ int   g_seg_start[MAXN];
static __device__ int   g_seg_end[MAXN];
static __device__ float g_wta[IN_DIM];
static __device__ float g_ct;
static __device__ int   g_idx64;

// ---------------- index dtype handling -------------------------------------
__device__ __forceinline__ int IDX(const void* p, int i, int is64) {
    if (is64) return (int)(((const long long*)p)[i]);
    return ((const int*)p)[i];
}

// usrc is sorted unique node ids (strictly increasing, small values).
// int64 layout as int32 words: [v0_lo, 0, v1_lo, 0, ...]; int32: [v0, v1, v2, v3].
__global__ void k_detect(const void* usrc) {
    const int* p = (const int*)usrc;
    g_idx64 = (p[1] == 0 && p[3] == 0) ? 1 : 0;
}

__global__ void k_init(int Ns, int E) {
    int i = blockIdx.x * blockDim.x + threadIdx.x;
    if (i < Ns) { g_seg_start[i] = E; g_seg_end[i] = 0; }
}

// wta[k] = sum_o Wt[k,o] * Wa[O+o];  ct = sum_o bt[o]*Wa[O+o]
__global__ void k_wta(const float* __restrict__ Wt, const float* __restrict__ bt,
                      const float* __restrict__ Wa) {
    int k = threadIdx.x;  // 256 threads
    const float* wrow = Wt + (long)k * OUT_DIM;
    float s = 0.f;
    for (int o = 0; o < OUT_DIM; o++) s = fmaf(wrow[o], Wa[OUT_DIM + o], s);
    g_wta[k] = s;
    __shared__ float red[OUT_DIM];
    red[k] = bt[k] * Wa[OUT_DIM + k];
    __syncthreads();
    for (int st = OUT_DIM / 2; st > 0; st >>= 1) {
        if (k < st) red[k] += red[k + st];
        __syncthreads();
    }
    if (k == 0) g_ct = red[0];
}

// ---------------- gathered SGEMM: C[m, :] = nodes[gather(m), :] @ W + bias --
// M = unique_count * BATCH; row m -> node uidx[m/BATCH], batch m%BATCH.
// 128x128 tile, BK=8, 256 threads, 8x8 accumulators per thread.
__global__ __launch_bounds__(256, 2) void k_gemm_gather(
    const float* __restrict__ nodes, const void* __restrict__ uidx,
    const float* __restrict__ W, const float* __restrict__ bias,
    int M, int which)   // which: 0 -> g_src_proj, 1 -> g_vals
{
    __shared__ float As[8][128];
    __shared__ float Bs[8][128];
    float* __restrict__ C = which ? g_vals : g_src_proj;

    const int t = threadIdx.x;
    const int is64 = g_idx64;
    const int tile_m = blockIdx.x * 128;
    const int tile_n = blockIdx.y * 128;

    // A: 128 rows x 8 k; thread loads one float4 (row = t>>1, kc = (t&1)*4)
    const int arow = t >> 1;
    const int akc  = (t & 1) * 4;
    const int m = tile_m + arow;
    const bool avalid = (m < M);
    const float* aptr = nodes;
    if (avalid) {
        int nidx = m / BATCH, b = m - nidx * BATCH;
        long g = (long)IDX(uidx, nidx, is64) * BATCH + b;
        aptr = nodes + g * IN_DIM;
    }
    // B: 8 rows x 128 cols; thread loads one float4 (row = t>>5, col = (t&31)*4)
    const int bkr  = t >> 5;
    const int bcol = (t & 31) * 4;
    const float* bptr = W + (long)bkr * OUT_DIM + tile_n + bcol;

    const int ty = t >> 4, tx = t & 15;
    float acc[8][8];
#pragma unroll
    for (int i = 0; i < 8; i++)
#pragma unroll
        for (int j = 0; j < 8; j++) acc[i][j] = 0.f;

    for (int kt = 0; kt < IN_DIM / 8; kt++) {
        float4 av = avalid ? *reinterpret_cast<const float4*>(aptr + kt * 8 + akc)
                           : make_float4(0.f, 0.f, 0.f, 0.f);
        float4 bv = *reinterpret_cast<const float4*>(bptr + (long)kt * 8 * OUT_DIM);
        As[akc + 0][arow] = av.x;
        As[akc + 1][arow] = av.y;
        As[akc + 2][arow] = av.z;
        As[akc + 3][arow] = av.w;
        *reinterpret_cast<float4*>(&Bs[bkr][bcol]) = bv;
        __syncthreads();
#pragma unroll
        for (int k = 0; k < 8; k++) {
            float a[8], b[8];
            *reinterpret_cast<float4*>(a)     = *reinterpret_cast<const float4*>(&As[k][ty * 8]);
            *reinterpret_cast<float4*>(a + 4) = *reinterpret_cast<const float4*>(&As[k][ty * 8 + 4]);
            *reinterpret_cast<float4*>(b)     = *reinterpret_cast<const float4*>(&Bs[k][tx * 8]);
            *reinterpret_cast<float4*>(b + 4) = *reinterpret_cast<const float4*>(&Bs[k][tx * 8 + 4]);
#pragma unroll
            for (int i = 0; i < 8; i++)
#pragma unroll
                for (int j = 0; j < 8; j++) acc[i][j] = fmaf(a[i], b[j], acc[i][j]);
        }
        __syncthreads();
    }

#pragma unroll
    for (int i = 0; i < 8; i++) {
        int r = tile_m + ty * 8 + i;
        if (r < M) {
            int c0 = tile_n + tx * 8;
            float* cp = C + (long)r * OUT_DIM + c0;
            float4 o0, o1;
            o0.x = acc[i][0] + bias[c0 + 0];
            o0.y = acc[i][1] + bias[c0 + 1];
            o0.z = acc[i][2] + bias[c0 + 2];
            o0.w = acc[i][3] + bias[c0 + 3];
            o1.x = acc[i][4] + bias[c0 + 4];
            o1.y = acc[i][5] + bias[c0 + 5];
            o1.z = acc[i][6] + bias[c0 + 6];
            o1.w = acc[i][7] + bias[c0 + 7];
            *reinterpret_cast<float4*>(cp)     = o0;
            *reinterpret_cast<float4*>(cp + 4) = o1;
        }
    }
}

// sdot[m] = src_proj[m,:] . Wa[0:O]   (warp per row)
__global__ void k_sdot(const float* __restrict__ Wa, int Mrows) {
    int w = (blockIdx.x * blockDim.x + threadIdx.x) >> 5;
    int lane = threadIdx.x & 31;
    if (w >= Mrows) return;
    const float* row = g_src_proj + (long)w * OUT_DIM;
    float s = 0.f;
#pragma unroll
    for (int o = lane; o < OUT_DIM; o += 32) s = fmaf(row[o], Wa[o], s);
#pragma unroll
    for (int st = 16; st; st >>= 1) s += __shfl_xor_sync(0xFFFFFFFFu, s, st);
    if (lane == 0) g_sdot[w] = s;
}

// tdot[m] = nodes[gather(m),:] . wta + ct   (warp per row)
__global__ void k_tdot(const float* __restrict__ nodes, const void* __restrict__ utgt,
                       int Mrows) {
    int w = (blockIdx.x * blockDim.x + threadIdx.x) >> 5;
    int lane = threadIdx.x & 31;
    if (w >= Mrows) return;
    int is64 = g_idx64;
    int nidx = w / BATCH, b = w - nidx * BATCH;
    long g = (long)IDX(utgt, nidx, is64) * BATCH + b;
    const float* row = nodes + g * IN_DIM;
    float s = 0.f;
#pragma unroll
    for (int o = lane; o < IN_DIM; o += 32) s = fmaf(row[o], g_wta[o], s);
#pragma unroll
    for (int st = 16; st; st >>= 1) s += __shfl_xor_sync(0xFFFFFFFFu, s, st);
    if (lane == 0) g_tdot[w] = s + g_ct;
}

// per-edge: score -> leaky_relu -> clip -> exp; also segment boundaries
__global__ void k_edge(const void* __restrict__ sidp, const void* __restrict__ tidp,
                       const float* __restrict__ ba, int E) {
    int e = blockIdx.x * blockDim.x + threadIdx.x;
    if (e >= E) return;
    int is64 = g_idx64;
    int s  = IDX(sidp, e, is64);
    int tg = IDX(tidp, e, is64);
    atomicMin(&g_seg_start[s], e);
    atomicMax(&g_seg_end[s], e + 1);
    float b0 = ba[0];
#pragma unroll
    for (int b = 0; b < BATCH; b++) {
        float sc = g_sdot[s * BATCH + b] + g_tdot[tg * BATCH + b] + b0;
        sc = (sc >= 0.f) ? sc : SLOPE * sc;
        sc = fminf(2.f, fmaxf(-2.f, sc));
        g_ex[e * BATCH + b] = expf(sc);
    }
}

// deterministic segment-sum of ex over each source's contiguous edge range
__global__ void k_denom(int Ns) {
    int i = blockIdx.x * blockDim.x + threadIdx.x;
    if (i >= Ns * BATCH) return;
    int n = i / BATCH, b = i - (i / BATCH) * BATCH;
    int s0 = g_seg_start[n], s1 = g_seg_end[n];
    float d = 0.f;
    for (int e = s0; e < s1; e++) d += g_ex[e * BATCH + b];
    g_denom[i] = d;
}

// alpha = ex / denom[sid]  (in place)
__global__ void k_alpha(const void* __restrict__ sidp, int E) {
    int e = blockIdx.x * blockDim.x + threadIdx.x;
    if (e >= E) return;
    int s = IDX(sidp, e, g_idx64);
#pragma unroll
    for (int b = 0; b < BATCH; b++)
        g_ex[e * BATCH + b] /= g_denom[s * BATCH + b];
}

// out[n,b,:] = src_proj[n,b,:] + sum_{e in seg(n)} alpha[tid[e],b] * vals[tid[tid[e]],b,:]
__global__ __launch_bounds__(256) void k_agg(const void* __restrict__ tidp,
                                             float* __restrict__ out, int Ns) {
    __shared__ float w0s[32], w1s[32];
    __shared__ int rows[32];
    int n = blockIdx.x;
    int o = threadIdx.x;
    int is64 = g_idx64;
    int s0 = g_seg_start[n], s1 = g_seg_end[n];
    float acc0 = g_src_proj[((long)n * BATCH + 0) * OUT_DIM + o];
    float acc1 = g_src_proj[((long)n * BATCH + 1) * OUT_DIM + o];
    for (int base = s0; base < s1; base += 32) {
        int cnt = min(32, s1 - base);
        if (o < cnt) {
            int j = IDX(tidp, base + o, is64);   // j = tid[e]
            w0s[o] = g_ex[j * BATCH + 0];
            w1s[o] = g_ex[j * BATCH + 1];
            rows[o] = IDX(tidp, j, is64);        // tid[tid[e]]
        }
        __syncthreads();
        for (int i = 0; i < cnt; i++) {
            int r = rows[i];
            acc0 = fmaf(w0s[i], g_vals[((long)r * BATCH + 0) * OUT_DIM + o], acc0);
            acc1 = fmaf(w1s[i], g_vals[((long)r * BATCH + 1) * OUT_DIM + o], acc1);
        }
        __syncthreads();
    }
    out[((long)n * BATCH + 0) * OUT_DIM + o] = acc0;
    out[((long)n * BATCH + 1) * OUT_DIM + o] = acc1;
}

extern "C" void kernel_launch(void* const* d_in, const int* in_sizes, int n_in,
                              void* d_out, int out_size) {
    const float* nodes = (const float*)d_in[0];
    const float* Ws    = (const float*)d_in[1];
    const float* bs    = (const float*)d_in[2];
    const float* Wt    = (const float*)d_in[3];
    const float* bt    = (const float*)d_in[4];
    const float* Wv    = (const float*)d_in[5];
    const float* bv    = (const float*)d_in[6];
    const float* Wa    = (const float*)d_in[7];
    const float* ba    = (const float*)d_in[8];
    const void* usrc   = d_in[9];
    const void* utgt   = d_in[10];
    const void* sidp   = d_in[11];
    const void* tidp   = d_in[12];

    const int Ns = in_sizes[9];
    const int Nt = in_sizes[10];
    const int E  = in_sizes[11];
    float* out = (float*)d_out;

    k_detect<<<1, 1>>>(usrc);
    k_init<<<(Ns + 255) / 256, 256>>>(Ns, E);
    k_wta<<<1, 256>>>(Wt, bt, Wa);

    const int Ms = Ns * BATCH;
    const int Mt = Nt * BATCH;

    dim3 gs((Ms + 127) / 128, OUT_DIM / 128);
    k_gemm_gather<<<gs, 256>>>(nodes, usrc, Ws, bs, Ms, 0);   // src_proj
    dim3 gv((Mt + 127) / 128, OUT_DIM / 128);
    k_gemm_gather<<<gv, 256>>>(nodes, utgt, Wv, bv, Mt, 1);   // vals

    k_sdot<<<(Ms * 32 + 255) / 256, 256>>>(Wa, Ms);
    k_tdot<<<(Mt * 32 + 255) / 256, 256>>>(nodes, utgt, Mt);

    k_edge<<<(E + 255) / 256, 256>>>(sidp, tidp, ba, E);
    k_denom<<<(Ns * BATCH + 255) / 256, 256>>>(Ns);
    k_alpha<<<(E + 255) / 256, 256>>>(sidp, E);

    k_agg<<<Ns, 256>>>(tidp, out, Ns);
}

// round 3
// speedup vs baseline: 1.7553x; 1.7553x over previous
#include <cuda_runtime.h>
#include <math.h>
#include <stdint.h>

#define IN_DIM 256
#define OUT_DIM 256
#define BATCH 2
#define MAXN 10240
#define MAXE 163840
#define SLOPE 0.2f

// ---------------- scratch (static device globals; no allocation) ----------
static __device__ float g_src_proj[MAXN * BATCH * OUT_DIM];   // 20 MB
static __device__ float g_vals[MAXN * BATCH * OUT_DIM];       // 20 MB
static __device__ float g_sdot[MAXN * BATCH];
static __device__ float g_tdot[MAXN * BATCH];
static __device__ float g_denom[MAXN * BATCH];
static __device__ float g_ex[MAXE * BATCH];
static __device__ int   g_seg_start[MAXN];
static __device__ int   g_seg_end[MAXN];
static __device__ float g_wta[IN_DIM];
static __device__ float g_ct;
static __device__ int   g_idx64;

// ---------------- index dtype handling -------------------------------------
__device__ __forceinline__ int IDX(const void* p, int i, int is64) {
    if (is64) return (int)(((const long long*)p)[i]);
    return ((const int*)p)[i];
}

__global__ void k_detect(const void* usrc) {
    const int* p = (const int*)usrc;
    g_idx64 = (p[1] == 0 && p[3] == 0) ? 1 : 0;
}

__global__ void k_init(int Ns, int E) {
    int i = blockIdx.x * blockDim.x + threadIdx.x;
    if (i < Ns) { g_seg_start[i] = E; g_seg_end[i] = 0; }
}

// wta[k] = sum_o Wt[k,o] * Wa[O+o];  ct = sum_o bt[o]*Wa[O+o]
__global__ void k_wta(const float* __restrict__ Wt, const float* __restrict__ bt,
                      const float* __restrict__ Wa) {
    int k = threadIdx.x;
    const float* wrow = Wt + (long)k * OUT_DIM;
    float s = 0.f;
    for (int o = 0; o < OUT_DIM; o++) s = fmaf(wrow[o], Wa[OUT_DIM + o], s);
    g_wta[k] = s;
    __shared__ float red[OUT_DIM];
    red[k] = bt[k] * Wa[OUT_DIM + k];
    __syncthreads();
    for (int st = OUT_DIM / 2; st > 0; st >>= 1) {
        if (k < st) red[k] += red[k + st];
        __syncthreads();
    }
    if (k == 0) g_ct = red[0];
}

// ---------------- tf32 mma.sync gathered GEMM -------------------------------
// C[m, :] = nodes[gather(m), :] @ W + bias.  CTA tile 128x128, K chunk 32,
// cp.async double buffer. 8 warps, warp tile 32x64, mma.m16n8k8.tf32.
#define AS_STRIDE 36     // floats per A row (pad 4)
#define BS_STRIDE 136    // floats per B row (pad 8)
#define AS_FLOATS (128 * AS_STRIDE)   // 4608
#define BS_FLOATS (32 * BS_STRIDE)    // 4352
#define SM_FLOATS (2 * AS_FLOATS + 2 * BS_FLOATS)   // 17920 floats = 71680 B

__device__ __forceinline__ uint32_t smem_u32(const void* p) {
    uint32_t a;
    asm("{ .reg .u64 t; cvta.to.shared.u64 t, %1; cvt.u32.u64 %0, t; }" : "=r"(a) : "l"(p));
    return a;
}
#define CP_ASYNC16(smaddr, gptr) \
    asm volatile("cp.async.ca.shared.global [%0], [%1], 16;" :: "r"(smaddr), "l"(gptr))
#define CP_COMMIT() asm volatile("cp.async.commit_group;" ::: "memory")
#define CP_WAIT1()  asm volatile("cp.async.wait_group 1;" ::: "memory")
#define CP_WAIT0()  asm volatile("cp.async.wait_group 0;" ::: "memory")

__device__ __forceinline__ void mma_tf32(float* c, const uint32_t* a, uint32_t b0, uint32_t b1) {
    asm volatile(
        "mma.sync.aligned.m16n8k8.row.col.f32.tf32.tf32.f32 "
        "{%0,%1,%2,%3}, {%4,%5,%6,%7}, {%8,%9}, {%0,%1,%2,%3};"
        : "+f"(c[0]), "+f"(c[1]), "+f"(c[2]), "+f"(c[3])
        : "r"(a[0]), "r"(a[1]), "r"(a[2]), "r"(a[3]), "r"(b0), "r"(b1));
}

__global__ __launch_bounds__(256) void k_gemm_mma(
    const float* __restrict__ nodes, const void* __restrict__ uidx,
    const float* __restrict__ W, const float* __restrict__ bias,
    int M, int which)
{
    extern __shared__ float sm[];
    const int t = threadIdx.x;
    const int tile_m = blockIdx.x * 128;
    const int tile_n = blockIdx.y * 128;
    const int is64 = g_idx64;
    float* __restrict__ C = which ? g_vals : g_src_proj;

    // ---- load mappings ----
    // A: thread t -> row ar = t>>1, k-span 16 floats at (t&1)*16
    const int ar  = t >> 1;
    const int akk = (t & 1) * 16;
    const int mclamp = min(tile_m + ar, M - 1);
    const long gath = (long)IDX(uidx, mclamp >> 1, is64) * BATCH + (mclamp & 1);
    const float* __restrict__ aptr = nodes + gath * IN_DIM + akk;
    // B: thread t -> k row bk = t>>3, n-span 16 floats at (t&7)*16
    const int bk = t >> 3;
    const int bn = (t & 7) * 16;
    const float* __restrict__ bptr = W + (long)bk * OUT_DIM + tile_n + bn;

    const uint32_t sb = smem_u32(sm);
    const uint32_t a_sm_base = sb + (ar * AS_STRIDE + akk) * 4;
    const uint32_t b_sm_base = sb + (2 * AS_FLOATS + bk * BS_STRIDE + bn) * 4;

    // ---- fragment mapping ----
    const int wid = t >> 5, lane = t & 31;
    const int g = lane >> 2, tg = lane & 3;
    const int wm = (wid >> 1) * 32;     // warp m-offset (4 m-warps)
    const int wn = (wid & 1) * 64;      // warp n-offset (2 n-warps)

    float acc[2][8][4];
#pragma unroll
    for (int i = 0; i < 2; i++)
#pragma unroll
        for (int j = 0; j < 8; j++)
#pragma unroll
            for (int q = 0; q < 4; q++) acc[i][j][q] = 0.f;

    // ---- pipeline ----
    // issue chunk 0 into buf 0
#pragma unroll
    for (int q = 0; q < 4; q++) CP_ASYNC16(a_sm_base + q * 16, aptr + q * 4);
#pragma unroll
    for (int q = 0; q < 4; q++) CP_ASYNC16(b_sm_base + q * 16, bptr + q * 4);
    CP_COMMIT();

    for (int c = 0; c < 8; c++) {
        const int buf = c & 1;
        if (c < 7) {
            const int kb = (c + 1) * 32;
            const uint32_t abuf = a_sm_base + (buf ^ 1) * (AS_FLOATS * 4);
            const uint32_t bbuf = b_sm_base + (buf ^ 1) * (BS_FLOATS * 4);
#pragma unroll
            for (int q = 0; q < 4; q++) CP_ASYNC16(abuf + q * 16, aptr + kb + q * 4);
#pragma unroll
            for (int q = 0; q < 4; q++) CP_ASYNC16(bbuf + q * 16, bptr + (long)kb * OUT_DIM + q * 4);
            CP_COMMIT();
            CP_WAIT1();
        } else {
            CP_WAIT0();
        }
        __syncthreads();

        const float* __restrict__ A = sm + buf * AS_FLOATS;
        const float* __restrict__ B = sm + 2 * AS_FLOATS + buf * BS_FLOATS;
#pragma unroll
        for (int k0 = 0; k0 < 32; k0 += 8) {
            uint32_t a0[4], a1[4];
            a0[0] = __float_as_uint(A[(wm + g)      * AS_STRIDE + k0 + tg]);
            a0[1] = __float_as_uint(A[(wm + g + 8)  * AS_STRIDE + k0 + tg]);
            a0[2] = __float_as_uint(A[(wm + g)      * AS_STRIDE + k0 + tg + 4]);
            a0[3] = __float_as_uint(A[(wm + g + 8)  * AS_STRIDE + k0 + tg + 4]);
            a1[0] = __float_as_uint(A[(wm + 16 + g)     * AS_STRIDE + k0 + tg]);
            a1[1] = __float_as_uint(A[(wm + 16 + g + 8) * AS_STRIDE + k0 + tg]);
            a1[2] = __float_as_uint(A[(wm + 16 + g)     * AS_STRIDE + k0 + tg + 4]);
            a1[3] = __float_as_uint(A[(wm + 16 + g + 8) * AS_STRIDE + k0 + tg + 4]);
#pragma unroll
            for (int bx = 0; bx < 8; bx++) {
                uint32_t b0 = __float_as_uint(B[(k0 + tg)     * BS_STRIDE + wn + bx * 8 + g]);
                uint32_t b1 = __float_as_uint(B[(k0 + tg + 4) * BS_STRIDE + wn + bx * 8 + g]);
                mma_tf32(acc[0][bx], a0, b0, b1);
                mma_tf32(acc[1][bx], a1, b0, b1);
            }
        }
        __syncthreads();
    }

    // ---- epilogue ----
#pragma unroll
    for (int am = 0; am < 2; am++) {
        const int m0 = tile_m + wm + am * 16 + g;
        const int m1 = m0 + 8;
#pragma unroll
        for (int bx = 0; bx < 8; bx++) {
            const int col = tile_n + wn + bx * 8 + tg * 2;
            const float bi0 = bias[col], bi1 = bias[col + 1];
            if (m0 < M) {
                float2 v = make_float2(acc[am][bx][0] + bi0, acc[am][bx][1] + bi1);
                *reinterpret_cast<float2*>(C + (long)m0 * OUT_DIM + col) = v;
            }
            if (m1 < M) {
                float2 v = make_float2(acc[am][bx][2] + bi0, acc[am][bx][3] + bi1);
                *reinterpret_cast<float2*>(C + (long)m1 * OUT_DIM + col) = v;
            }
        }
    }
}

// sdot[m] = src_proj[m,:] . Wa[0:O]   (warp per row)
__global__ void k_sdot(const float* __restrict__ Wa, int Mrows) {
    int w = (blockIdx.x * blockDim.x + threadIdx.x) >> 5;
    int lane = threadIdx.x & 31;
    if (w >= Mrows) return;
    const float* row = g_src_proj + (long)w * OUT_DIM;
    float s = 0.f;
#pragma unroll
    for (int o = lane; o < OUT_DIM; o += 32) s = fmaf(row[o], Wa[o], s);
#pragma unroll
    for (int st = 16; st; st >>= 1) s += __shfl_xor_sync(0xFFFFFFFFu, s, st);
    if (lane == 0) g_sdot[w] = s;
}

// tdot[m] = nodes[gather(m),:] . wta + ct   (warp per row)
__global__ void k_tdot(const float* __restrict__ nodes, const void* __restrict__ utgt,
                       int Mrows) {
    int w = (blockIdx.x * blockDim.x + threadIdx.x) >> 5;
    int lane = threadIdx.x & 31;
    if (w >= Mrows) return;
    int is64 = g_idx64;
    int nidx = w / BATCH, b = w - nidx * BATCH;
    long gidx = (long)IDX(utgt, nidx, is64) * BATCH + b;
    const float* row = nodes + gidx * IN_DIM;
    float s = 0.f;
#pragma unroll
    for (int o = lane; o < IN_DIM; o += 32) s = fmaf(row[o], g_wta[o], s);
#pragma unroll
    for (int st = 16; st; st >>= 1) s += __shfl_xor_sync(0xFFFFFFFFu, s, st);
    if (lane == 0) g_tdot[w] = s + g_ct;
}

// per-edge: score -> leaky_relu -> clip -> exp; also segment boundaries
__global__ void k_edge(const void* __restrict__ sidp, const void* __restrict__ tidp,
                       const float* __restrict__ ba, int E) {
    int e = blockIdx.x * blockDim.x + threadIdx.x;
    if (e >= E) return;
    int is64 = g_idx64;
    int s  = IDX(sidp, e, is64);
    int tg = IDX(tidp, e, is64);
    atomicMin(&g_seg_start[s], e);
    atomicMax(&g_seg_end[s], e + 1);
    float b0 = ba[0];
#pragma unroll
    for (int b = 0; b < BATCH; b++) {
        float sc = g_sdot[s * BATCH + b] + g_tdot[tg * BATCH + b] + b0;
        sc = (sc >= 0.f) ? sc : SLOPE * sc;
        sc = fminf(2.f, fmaxf(-2.f, sc));
        g_ex[e * BATCH + b] = expf(sc);
    }
}

// deterministic segment-sum of ex over each source's contiguous edge range
__global__ void k_denom(int Ns) {
    int i = blockIdx.x * blockDim.x + threadIdx.x;
    if (i >= Ns * BATCH) return;
    int n = i / BATCH, b = i - (i / BATCH) * BATCH;
    int s0 = g_seg_start[n], s1 = g_seg_end[n];
    float d = 0.f;
    for (int e = s0; e < s1; e++) d += g_ex[e * BATCH + b];
    g_denom[i] = d;
}

// alpha = ex / denom[sid]  (in place)
__global__ void k_alpha(const void* __restrict__ sidp, int E) {
    int e = blockIdx.x * blockDim.x + threadIdx.x;
    if (e >= E) return;
    int s = IDX(sidp, e, g_idx64);
#pragma unroll
    for (int b = 0; b < BATCH; b++)
        g_ex[e * BATCH + b] /= g_denom[s * BATCH + b];
}

// out[n,b,:] = src_proj[n,b,:] + sum_{e in seg(n)} alpha[tid[e],b] * vals[tid[tid[e]],b,:]
__global__ __launch_bounds__(256) void k_agg(const void* __restrict__ tidp,
                                             float* __restrict__ out, int Ns) {
    __shared__ float w0s[32], w1s[32];
    __shared__ int rows[32];
    int n = blockIdx.x;
    int o = threadIdx.x;
    int is64 = g_idx64;
    int s0 = g_seg_start[n], s1 = g_seg_end[n];
    float acc0 = g_src_proj[((long)n * BATCH + 0) * OUT_DIM + o];
    float acc1 = g_src_proj[((long)n * BATCH + 1) * OUT_DIM + o];
    for (int base = s0; base < s1; base += 32) {
        int cnt = min(32, s1 - base);
        if (o < cnt) {
            int j = IDX(tidp, base + o, is64);   // j = tid[e]
            w0s[o] = g_ex[j * BATCH + 0];
            w1s[o] = g_ex[j * BATCH + 1];
            rows[o] = IDX(tidp, j, is64);        // tid[tid[e]]
        }
        __syncthreads();
        for (int i = 0; i < cnt; i++) {
            int r = rows[i];
            acc0 = fmaf(w0s[i], g_vals[((long)r * BATCH + 0) * OUT_DIM + o], acc0);
            acc1 = fmaf(w1s[i], g_vals[((long)r * BATCH + 1) * OUT_DIM + o], acc1);
        }
        __syncthreads();
    }
    out[((long)n * BATCH + 0) * OUT_DIM + o] = acc0;
    out[((long)n * BATCH + 1) * OUT_DIM + o] = acc1;
}

extern "C" void kernel_launch(void* const* d_in, const int* in_sizes, int n_in,
                              void* d_out, int out_size) {
    const float* nodes = (const float*)d_in[0];
    const float* Ws    = (const float*)d_in[1];
    const float* bs    = (const float*)d_in[2];
    const float* Wt    = (const float*)d_in[3];
    const float* bt    = (const float*)d_in[4];
    const float* Wv    = (const float*)d_in[5];
    const float* bv    = (const float*)d_in[6];
    const float* Wa    = (const float*)d_in[7];
    const float* ba    = (const float*)d_in[8];
    const void* usrc   = d_in[9];
    const void* utgt   = d_in[10];
    const void* sidp   = d_in[11];
    const void* tidp   = d_in[12];

    const int Ns = in_sizes[9];
    const int Nt = in_sizes[10];
    const int E  = in_sizes[11];
    float* out = (float*)d_out;

    static int smem_set = 0;
    if (!smem_set) {
        cudaFuncSetAttribute(k_gemm_mma, cudaFuncAttributeMaxDynamicSharedMemorySize,
                             SM_FLOATS * 4);
        smem_set = 1;
    }

    k_detect<<<1, 1>>>(usrc);
    k_init<<<(Ns + 255) / 256, 256>>>(Ns, E);
    k_wta<<<1, 256>>>(Wt, bt, Wa);

    const int Ms = Ns * BATCH;
    const int Mt = Nt * BATCH;

    dim3 gs((Ms + 127) / 128, OUT_DIM / 128);
    k_gemm_mma<<<gs, 256, SM_FLOATS * 4>>>(nodes, usrc, Ws, bs, Ms, 0);
    dim3 gv((Mt + 127) / 128, OUT_DIM / 128);
    k_gemm_mma<<<gv, 256, SM_FLOATS * 4>>>(nodes, utgt, Wv, bv, Mt, 1);

    k_sdot<<<(Ms * 32 + 255) / 256, 256>>>(Wa, Ms);
    k_tdot<<<(Mt * 32 + 255) / 256, 256>>>(nodes, utgt, Mt);

    k_edge<<<(E + 255) / 256, 256>>>(sidp, tidp, ba, E);
    k_denom<<<(Ns * BATCH + 255) / 256, 256>>>(Ns);
    k_alpha<<<(E + 255) / 256, 256>>>(sidp, E);

    k_agg<<<Ns, 256>>>(tidp, out, Ns);
}

// round 4
// speedup vs baseline: 2.3061x; 1.3137x over previous
#include <cuda_runtime.h>
#include <math.h>
#include <stdint.h>

#define IN_DIM 256
#define OUT_DIM 256
#define BATCH 2
#define MAXN 10240
#define MAXE 163840
#define SLOPE 0.2f

// ---------------- scratch (static device globals; no allocation) ----------
static __device__ float g_src_proj[MAXN * BATCH * OUT_DIM];   // 20 MB
static __device__ float g_vals[MAXN * BATCH * OUT_DIM];       // 20 MB
static __device__ float g_sdot[MAXN * BATCH];
static __device__ float g_tdot[MAXN * BATCH];
static __device__ float g_denom[MAXN * BATCH];
static __device__ float g_ex[MAXE * BATCH];
static __device__ int   g_seg_start[MAXN];
static __device__ int   g_seg_end[MAXN];
static __device__ float g_wta[IN_DIM];
static __device__ float g_ct;
static __device__ int   g_idx64;

// ---------------- index dtype handling -------------------------------------
__device__ __forceinline__ int IDX(const void* p, int i, int is64) {
    if (is64) return (int)(((const long long*)p)[i]);
    return ((const int*)p)[i];
}

// ---------------- fused prep: detect + seg init + wta + ct ------------------
// grid = Nblk + 1 + 32 blocks of 256 threads.
//  [0, Nblk)        : segment bound init
//  Nblk             : idx-dtype detect (t0) + ct reduction
//  (Nblk, Nblk+32]  : wta, warp per k (32 blocks x 8 warps = 256 warps)
__global__ void k_prep(const void* __restrict__ usrc,
                       const float* __restrict__ Wt, const float* __restrict__ bt,
                       const float* __restrict__ Wa, int Ns, int E, int Nblk) {
    const int bid = blockIdx.x;
    const int t = threadIdx.x;
    if (bid < Nblk) {
        int i = bid * 256 + t;
        if (i < Ns) { g_seg_start[i] = E; g_seg_end[i] = 0; }
    } else if (bid == Nblk) {
        if (t == 0) {
            const int* p = (const int*)usrc;
            g_idx64 = (p[1] == 0 && p[3] == 0) ? 1 : 0;
        }
        __shared__ float red[256];
        red[t] = bt[t] * Wa[OUT_DIM + t];
        __syncthreads();
        for (int st = 128; st > 0; st >>= 1) {
            if (t < st) red[t] += red[t + st];
            __syncthreads();
        }
        if (t == 0) g_ct = red[0];
    } else {
        const int k = (bid - Nblk - 1) * 8 + (t >> 5);
        const int lane = t & 31;
        const float* wrow = Wt + (long)k * OUT_DIM;
        float s = 0.f;
#pragma unroll
        for (int o = lane; o < OUT_DIM; o += 32) s = fmaf(wrow[o], Wa[OUT_DIM + o], s);
#pragma unroll
        for (int st = 16; st; st >>= 1) s += __shfl_xor_sync(0xFFFFFFFFu, s, st);
        if (lane == 0) g_wta[k] = s;
    }
}

// ---------------- tf32 mma.sync gathered GEMM (both GEMMs in one launch) ----
// z=0: g_src_proj = nodes[usrc gather] @ Ws + bs
// z=1: g_vals     = nodes[utgt gather] @ Wv + bv
#define AS_STRIDE 36     // floats per A row (pad 4)
#define BS_STRIDE 136    // floats per B row (pad 8)
#define AS_FLOATS (128 * AS_STRIDE)   // 4608
#define BS_FLOATS (32 * BS_STRIDE)    // 4352
#define SM_FLOATS (2 * AS_FLOATS + 2 * BS_FLOATS)   // 17920 floats = 71680 B

__device__ __forceinline__ uint32_t smem_u32(const void* p) {
    uint32_t a;
    asm("{ .reg .u64 t; cvta.to.shared.u64 t, %1; cvt.u32.u64 %0, t; }" : "=r"(a) : "l"(p));
    return a;
}
#define CP_ASYNC16(smaddr, gptr) \
    asm volatile("cp.async.ca.shared.global [%0], [%1], 16;" :: "r"(smaddr), "l"(gptr))
#define CP_COMMIT() asm volatile("cp.async.commit_group;" ::: "memory")
#define CP_WAIT1()  asm volatile("cp.async.wait_group 1;" ::: "memory")
#define CP_WAIT0()  asm volatile("cp.async.wait_group 0;" ::: "memory")

__device__ __forceinline__ void mma_tf32(float* c, const uint32_t* a, uint32_t b0, uint32_t b1) {
    asm volatile(
        "mma.sync.aligned.m16n8k8.row.col.f32.tf32.tf32.f32 "
        "{%0,%1,%2,%3}, {%4,%5,%6,%7}, {%8,%9}, {%0,%1,%2,%3};"
        : "+f"(c[0]), "+f"(c[1]), "+f"(c[2]), "+f"(c[3])
        : "r"(a[0]), "r"(a[1]), "r"(a[2]), "r"(a[3]), "r"(b0), "r"(b1));
}

__global__ __launch_bounds__(256) void k_gemm_mma(
    const float* __restrict__ nodes,
    const void* __restrict__ usrc, const void* __restrict__ utgt,
    const float* __restrict__ Ws, const float* __restrict__ Wv,
    const float* __restrict__ bs, const float* __restrict__ bv,
    int Ms, int Mt)
{
    extern __shared__ float sm[];
    const int which = blockIdx.z;
    const void* __restrict__ uidx = which ? utgt : usrc;
    const float* __restrict__ W = which ? Wv : Ws;
    const float* __restrict__ bias = which ? bv : bs;
    const int M = which ? Mt : Ms;
    float* __restrict__ C = which ? g_vals : g_src_proj;

    const int t = threadIdx.x;
    const int tile_m = blockIdx.x * 128;
    const int tile_n = blockIdx.y * 128;
    if (tile_m >= M) return;
    const int is64 = g_idx64;

    // ---- load mappings ----
    const int ar  = t >> 1;
    const int akk = (t & 1) * 16;
    const int mclamp = min(tile_m + ar, M - 1);
    const long gath = (long)IDX(uidx, mclamp >> 1, is64) * BATCH + (mclamp & 1);
    const float* __restrict__ aptr = nodes + gath * IN_DIM + akk;
    const int bk = t >> 3;
    const int bn = (t & 7) * 16;
    const float* __restrict__ bptr = W + (long)bk * OUT_DIM + tile_n + bn;

    const uint32_t sb = smem_u32(sm);
    const uint32_t a_sm_base = sb + (ar * AS_STRIDE + akk) * 4;
    const uint32_t b_sm_base = sb + (2 * AS_FLOATS + bk * BS_STRIDE + bn) * 4;

    // ---- fragment mapping ----
    const int wid = t >> 5, lane = t & 31;
    const int g = lane >> 2, tg = lane & 3;
    const int wm = (wid >> 1) * 32;
    const int wn = (wid & 1) * 64;

    float acc[2][8][4];
#pragma unroll
    for (int i = 0; i < 2; i++)
#pragma unroll
        for (int j = 0; j < 8; j++)
#pragma unroll
            for (int q = 0; q < 4; q++) acc[i][j][q] = 0.f;

    // ---- pipeline ----
#pragma unroll
    for (int q = 0; q < 4; q++) CP_ASYNC16(a_sm_base + q * 16, aptr + q * 4);
#pragma unroll
    for (int q = 0; q < 4; q++) CP_ASYNC16(b_sm_base + q * 16, bptr + q * 4);
    CP_COMMIT();

    for (int c = 0; c < 8; c++) {
        const int buf = c & 1;
        if (c < 7) {
            const int kb = (c + 1) * 32;
            const uint32_t abuf = a_sm_base + (buf ^ 1) * (AS_FLOATS * 4);
            const uint32_t bbuf = b_sm_base + (buf ^ 1) * (BS_FLOATS * 4);
#pragma unroll
            for (int q = 0; q < 4; q++) CP_ASYNC16(abuf + q * 16, aptr + kb + q * 4);
#pragma unroll
            for (int q = 0; q < 4; q++) CP_ASYNC16(bbuf + q * 16, bptr + (long)kb * OUT_DIM + q * 4);
            CP_COMMIT();
            CP_WAIT1();
        } else {
            CP_WAIT0();
        }
        __syncthreads();

        const float* __restrict__ A = sm + buf * AS_FLOATS;
        const float* __restrict__ B = sm + 2 * AS_FLOATS + buf * BS_FLOATS;
#pragma unroll
        for (int k0 = 0; k0 < 32; k0 += 8) {
            uint32_t a0[4], a1[4];
            a0[0] = __float_as_uint(A[(wm + g)      * AS_STRIDE + k0 + tg]);
            a0[1] = __float_as_uint(A[(wm + g + 8)  * AS_STRIDE + k0 + tg]);
            a0[2] = __float_as_uint(A[(wm + g)      * AS_STRIDE + k0 + tg + 4]);
            a0[3] = __float_as_uint(A[(wm + g + 8)  * AS_STRIDE + k0 + tg + 4]);
            a1[0] = __float_as_uint(A[(wm + 16 + g)     * AS_STRIDE + k0 + tg]);
            a1[1] = __float_as_uint(A[(wm + 16 + g + 8) * AS_STRIDE + k0 + tg]);
            a1[2] = __float_as_uint(A[(wm + 16 + g)     * AS_STRIDE + k0 + tg + 4]);
            a1[3] = __float_as_uint(A[(wm + 16 + g + 8) * AS_STRIDE + k0 + tg + 4]);
#pragma unroll
            for (int bx = 0; bx < 8; bx++) {
                uint32_t b0 = __float_as_uint(B[(k0 + tg)     * BS_STRIDE + wn + bx * 8 + g]);
                uint32_t b1 = __float_as_uint(B[(k0 + tg + 4) * BS_STRIDE + wn + bx * 8 + g]);
                mma_tf32(acc[0][bx], a0, b0, b1);
                mma_tf32(acc[1][bx], a1, b0, b1);
            }
        }
        __syncthreads();
    }

    // ---- epilogue ----
#pragma unroll
    for (int am = 0; am < 2; am++) {
        const int m0 = tile_m + wm + am * 16 + g;
        const int m1 = m0 + 8;
#pragma unroll
        for (int bx = 0; bx < 8; bx++) {
            const int col = tile_n + wn + bx * 8 + tg * 2;
            const float bi0 = bias[col], bi1 = bias[col + 1];
            if (m0 < M) {
                float2 v = make_float2(acc[am][bx][0] + bi0, acc[am][bx][1] + bi1);
                *reinterpret_cast<float2*>(C + (long)m0 * OUT_DIM + col) = v;
            }
            if (m1 < M) {
                float2 v = make_float2(acc[am][bx][2] + bi0, acc[am][bx][3] + bi1);
                *reinterpret_cast<float2*>(C + (long)m1 * OUT_DIM + col) = v;
            }
        }
    }
}

// ---------------- merged sdot/tdot (warp per row) ---------------------------
// w < Ms           : g_sdot[w] = src_proj[w,:] . Wa[0:O]
// Ms <= w < Ms+Mt  : g_tdot[w-Ms] = nodes[gather(w-Ms),:] . wta + ct
__global__ void k_dots(const float* __restrict__ nodes, const void* __restrict__ utgt,
                       const float* __restrict__ Wa, int Ms, int Mt) {
    int w = (blockIdx.x * blockDim.x + threadIdx.x) >> 5;
    int lane = threadIdx.x & 31;
    if (w < Ms) {
        const float* row = g_src_proj + (long)w * OUT_DIM;
        float s = 0.f;
#pragma unroll
        for (int o = lane; o < OUT_DIM; o += 32) s = fmaf(row[o], Wa[o], s);
#pragma unroll
        for (int st = 16; st; st >>= 1) s += __shfl_xor_sync(0xFFFFFFFFu, s, st);
        if (lane == 0) g_sdot[w] = s;
    } else if (w < Ms + Mt) {
        int m = w - Ms;
        int is64 = g_idx64;
        int nidx = m >> 1, b = m & 1;
        long gidx = (long)IDX(utgt, nidx, is64) * BATCH + b;
        const float* row = nodes + gidx * IN_DIM;
        float s = 0.f;
#pragma unroll
        for (int o = lane; o < IN_DIM; o += 32) s = fmaf(row[o], g_wta[o], s);
#pragma unroll
        for (int st = 16; st; st >>= 1) s += __shfl_xor_sync(0xFFFFFFFFu, s, st);
        if (lane == 0) g_tdot[m] = s + g_ct;
    }
}

// per-edge: score -> leaky_relu -> clip -> exp; also segment boundaries
__global__ void k_edge(const void* __restrict__ sidp, const void* __restrict__ tidp,
                       const float* __restrict__ ba, int E) {
    int e = blockIdx.x * blockDim.x + threadIdx.x;
    if (e >= E) return;
    int is64 = g_idx64;
    int s  = IDX(sidp, e, is64);
    int tg = IDX(tidp, e, is64);
    atomicMin(&g_seg_start[s], e);
    atomicMax(&g_seg_end[s], e + 1);
    float b0 = ba[0];
#pragma unroll
    for (int b = 0; b < BATCH; b++) {
        float sc = g_sdot[s * BATCH + b] + g_tdot[tg * BATCH + b] + b0;
        sc = (sc >= 0.f) ? sc : SLOPE * sc;
        sc = fminf(2.f, fmaxf(-2.f, sc));
        g_ex[e * BATCH + b] = expf(sc);
    }
}

// deterministic segment-sum of ex over each source's contiguous edge range
__global__ void k_denom(int Ns) {
    int i = blockIdx.x * blockDim.x + threadIdx.x;
    if (i >= Ns * BATCH) return;
    int n = i / BATCH, b = i - (i / BATCH) * BATCH;
    int s0 = g_seg_start[n], s1 = g_seg_end[n];
    float d = 0.f;
    for (int e = s0; e < s1; e++) d += g_ex[e * BATCH + b];
    g_denom[i] = d;
}

// alpha = ex / denom[sid]  (in place)
__global__ void k_alpha(const void* __restrict__ sidp, int E) {
    int e = blockIdx.x * blockDim.x + threadIdx.x;
    if (e >= E) return;
    int s = IDX(sidp, e, g_idx64);
#pragma unroll
    for (int b = 0; b < BATCH; b++)
        g_ex[e * BATCH + b] /= g_denom[s * BATCH + b];
}

// out[n,b,:] = src_proj[n,b,:] + sum_{e in seg(n)} alpha[tid[e],b] * vals[tid[tid[e]],b,:]
// 512 threads: b = t>>8, o = t&255. Two-way split accumulator for MLP.
__global__ __launch_bounds__(512) void k_agg(const void* __restrict__ tidp,
                                             float* __restrict__ out, int Ns) {
    __shared__ float ws[2][32];
    __shared__ int rows[32];
    const int n = blockIdx.x;
    const int t = threadIdx.x;
    const int b = t >> 8;
    const int o = t & 255;
    const int is64 = g_idx64;
    const int s0 = g_seg_start[n], s1 = g_seg_end[n];
    const long outrow = ((long)n * BATCH + b) * OUT_DIM + o;
    float accA = g_src_proj[outrow];
    float accB = 0.f;
    for (int base = s0; base < s1; base += 32) {
        int cnt = min(32, s1 - base);
        if (t < cnt) {
            int j = IDX(tidp, base + t, is64);   // j = tid[e]
            ws[0][t] = g_ex[j * BATCH + 0];
            ws[1][t] = g_ex[j * BATCH + 1];
            rows[t] = IDX(tidp, j, is64);        // tid[tid[e]]
        }
        __syncthreads();
        int i = 0;
        for (; i + 2 <= cnt; i += 2) {
            int r0 = rows[i], r1 = rows[i + 1];
            accA = fmaf(ws[b][i],     g_vals[((long)r0 * BATCH + b) * OUT_DIM + o], accA);
            accB = fmaf(ws[b][i + 1], g_vals[((long)r1 * BATCH + b) * OUT_DIM + o], accB);
        }
        if (i < cnt) {
            int r = rows[i];
            accA = fmaf(ws[b][i], g_vals[((long)r * BATCH + b) * OUT_DIM + o], accA);
        }
        __syncthreads();
    }
    out[outrow] = accA + accB;
}

extern "C" void kernel_launch(void* const* d_in, const int* in_sizes, int n_in,
                              void* d_out, int out_size) {
    const float* nodes = (const float*)d_in[0];
    const float* Ws    = (const float*)d_in[1];
    const float* bs    = (const float*)d_in[2];
    const float* Wt    = (const float*)d_in[3];
    const float* bt    = (const float*)d_in[4];
    const float* Wv    = (const float*)d_in[5];
    const float* bv    = (const float*)d_in[6];
    const float* Wa    = (const float*)d_in[7];
    const float* ba    = (const float*)d_in[8];
    const void* usrc   = d_in[9];
    const void* utgt   = d_in[10];
    const void* sidp   = d_in[11];
    const void* tidp   = d_in[12];

    const int Ns = in_sizes[9];
    const int Nt = in_sizes[10];
    const int E  = in_sizes[11];
    float* out = (float*)d_out;

    static int smem_set = 0;
    if (!smem_set) {
        cudaFuncSetAttribute(k_gemm_mma, cudaFuncAttributeMaxDynamicSharedMemorySize,
                             SM_FLOATS * 4);
        smem_set = 1;
    }

    const int Ms = Ns * BATCH;
    const int Mt = Nt * BATCH;
    const int Nblk = (Ns + 255) / 256;

    k_prep<<<Nblk + 1 + 32, 256>>>(usrc, Wt, bt, Wa, Ns, E, Nblk);

    const int Mmax = (Ms > Mt) ? Ms : Mt;
    dim3 gg((Mmax + 127) / 128, OUT_DIM / 128, 2);
    k_gemm_mma<<<gg, 256, SM_FLOATS * 4>>>(nodes, usrc, utgt, Ws, Wv, bs, bv, Ms, Mt);

    k_dots<<<((Ms + Mt) * 32 + 255) / 256, 256>>>(nodes, utgt, Wa, Ms, Mt);

    k_edge<<<(E + 255) / 256, 256>>>(sidp, tidp, ba, E);
    k_denom<<<(Ns * BATCH + 255) / 256, 256>>>(Ns);
    k_alpha<<<(E + 255) / 256, 256>>>(sidp, E);

    k_agg<<<Ns, 512>>>(tidp, out, Ns);
}